// round 6
// baseline (speedup 1.0000x reference)
#include <cuda_runtime.h>
#include <cuda_fp16.h>
#include <cstdint>

#define B_SZ 8192
#define D_SZ 256
#define NCLS 512
#define MAXM 128
#define MAXC 48
#define TM 64
#define MARGIN 1.0f
#define BIGF 1e9f

#define TILE_BYTES 16384                   // 128 rows * 128B
#define STAGE_BYTES (3 * TILE_BYTES)       // Ah, Bh, Bl
#define SMEM_DYN (2 * STAGE_BYTES + 1024)  // 97.25 KB -> 2 CTAs/SM
#define CLS_SMEM (MAXC * D_SZ * 4)         // 48KB -> 4 CTAs/SM

// ---------------- device scratch ----------------
__device__ float        g_e[B_SZ * D_SZ];
__device__ __half       g_hi[B_SZ * D_SZ];
__device__ __half       g_lo[B_SZ * D_SZ];
__device__ unsigned int g_hn_bits[B_SZ];
__device__ int          g_cls_cnt[NCLS];
__device__ int          g_cls_members[NCLS * MAXM];
__device__ float        g_total;
__device__ int          g_count;
__device__ int          g_lab64;

// ---------------- helpers ----------------
__device__ __forceinline__ uint32_t smem_u32(const void* p) {
    uint32_t a;
    asm("{ .reg .u64 t; cvta.to.shared.u64 t, %1; cvt.u32.u64 %0, t; }" : "=r"(a) : "l"(p));
    return a;
}
__device__ __forceinline__ int get_label(const int* l, int i, int is64) {
    return is64 ? l[2 * i] : l[i];
}

#define LDSM4(r0, r1, r2, r3, addr)                                              \
    asm volatile("ldmatrix.sync.aligned.m8n8.x4.shared.b16 {%0,%1,%2,%3}, [%4];" \
                 : "=r"(r0), "=r"(r1), "=r"(r2), "=r"(r3) : "r"(addr))

#define MMA16816(d, a0, a1, a2, a3, b0, b1)                                  \
    asm volatile("mma.sync.aligned.m16n8k16.row.col.f32.f16.f16.f32 "        \
                 "{%0,%1,%2,%3}, {%4,%5,%6,%7}, {%8,%9}, {%0,%1,%2,%3};"     \
                 : "+f"(d[0]), "+f"(d[1]), "+f"(d[2]), "+f"(d[3])            \
                 : "r"(a0), "r"(a1), "r"(a2), "r"(a3), "r"(b0), "r"(b1))

#define CPA16(dst, src)                                                       \
    asm volatile("cp.async.cg.shared.global [%0], [%1], 16;"                  \
                 :: "r"(dst), "l"(src) : "memory")
#define CPA_COMMIT asm volatile("cp.async.commit_group;" ::: "memory")
#define CPA_WAIT(n) asm volatile("cp.async.wait_group %0;" :: "n"(n) : "memory")

// ---------------- pre: detect label dtype + reset state ----------------
__global__ void pre_k(const int* __restrict__ labels) {
    if (blockIdx.x == 0) {
        __shared__ int sh[256];
        int acc = 0;
        for (int i = threadIdx.x; i < B_SZ / 2; i += 256) acc |= labels[2 * i + 1];
        sh[threadIdx.x] = acc;
        __syncthreads();
        for (int o = 128; o; o >>= 1) {
            if (threadIdx.x < o) sh[threadIdx.x] |= sh[threadIdx.x + o];
            __syncthreads();
        }
        if (threadIdx.x == 0) g_lab64 = (sh[0] == 0) ? 1 : 0;
    } else {
        int t = (blockIdx.x - 1) * 256 + threadIdx.x;
        if (t < B_SZ) g_hn_bits[t] = __float_as_uint(BIGF);
        if (t < NCLS) g_cls_cnt[t] = 0;
        if (t == 0) { g_total = 0.0f; g_count = 0; }
    }
}

// ---------------- normalize (warp/row) + fp16 split + class bucketing ----------------
__global__ __launch_bounds__(256) void normalize_k(const float* __restrict__ x,
                                                   const int* __restrict__ labels) {
    int wid = threadIdx.x >> 5, lane = threadIdx.x & 31;
    int row = blockIdx.x * 8 + wid;
    size_t base = (size_t)row * D_SZ + lane * 8;
    float4 v0 = *(const float4*)(x + base);
    float4 v1 = *(const float4*)(x + base + 4);
    float e[8] = {v0.x, v0.y, v0.z, v0.w, v1.x, v1.y, v1.z, v1.w};
    float s = 0.0f;
#pragma unroll
    for (int q = 0; q < 8; q++) s += e[q] * e[q];
#pragma unroll
    for (int o = 16; o; o >>= 1) s += __shfl_xor_sync(0xFFFFFFFFu, s, o);
    float inv = 1.0f / fmaxf(sqrtf(s), 1e-12f);

    union { __half h[8]; uint4 u; } hi, lo;
#pragma unroll
    for (int q = 0; q < 8; q++) {
        e[q] *= inv;
        __half h = __float2half_rn(e[q]);
        hi.h[q] = h;
        lo.h[q] = __float2half_rn(e[q] - __half2float(h));
    }
    *(float4*)(g_e + base)     = make_float4(e[0], e[1], e[2], e[3]);
    *(float4*)(g_e + base + 4) = make_float4(e[4], e[5], e[6], e[7]);
    *(uint4*)(g_hi + base) = hi.u;
    *(uint4*)(g_lo + base) = lo.u;

    if (lane == 0) {
        int c = get_label(labels, row, g_lab64);
        int p = atomicAdd(&g_cls_cnt[c], 1);
        if (p < MAXM) g_cls_members[c * MAXM + p] = row;
    }
}

// ---------------- HMMA GEMM + masked min (unchanged from R5) ----------------
__device__ __forceinline__ void issue_chunk(uint32_t sbase, int chunk, int ib, int jb,
                                            int tid) {
#pragma unroll
    for (int r = 0; r < 4; r++) {
        int idx = tid + 256 * r;
        int row = idx >> 3, seg = idx & 7;
        size_t gofs = (size_t)row * 512 + (size_t)chunk * 128 + (size_t)seg * 16;
        uint32_t off = (uint32_t)(row * 128 + ((seg * 16) ^ ((row & 7) << 4)));
        CPA16(sbase + 0 * TILE_BYTES + off, (const char*)g_hi + (size_t)ib * 512 + gofs);
        CPA16(sbase + 1 * TILE_BYTES + off, (const char*)g_hi + (size_t)jb * 512 + gofs);
        CPA16(sbase + 2 * TILE_BYTES + off, (const char*)g_lo + (size_t)jb * 512 + gofs);
    }
    CPA_COMMIT;
}

__global__ __launch_bounds__(256, 2) void min_gemm_hmma(const int* __restrict__ labels) {
    extern __shared__ char dyn[];
    __shared__ int   labA[128], labB[128];
    __shared__ float s_rmin[128][4];
    __shared__ float s_cmin[128][2];

    int bid = blockIdx.x;
    int bi = 0;
    while (((bi + 1) * (2 * TM - bi)) / 2 <= bid) bi++;
    int bj = bi + (bid - (bi * (2 * TM - bi + 1)) / 2);
    int ib = bi * 128, jb = bj * 128;

    int tid = threadIdx.x;
    int lane = tid & 31, wid = tid >> 5;
    int wr = wid >> 2, wc = wid & 3;
    int rbase = wr * 64, cbase = wc * 32;
    int is64 = g_lab64;

    uint32_t dbase = smem_u32(dyn);
    uint32_t tb = (dbase + 1023u) & ~1023u;

    if (tid < 128) labA[tid] = get_label(labels, ib + tid, is64);
    else           labB[tid - 128] = get_label(labels, jb + (tid - 128), is64);

    issue_chunk(tb, 0, ib, jb, tid);

    float acc[4][4][4];
#pragma unroll
    for (int mf = 0; mf < 4; mf++)
#pragma unroll
        for (int nf = 0; nf < 4; nf++)
#pragma unroll
            for (int r = 0; r < 4; r++) acc[mf][nf][r] = 0.0f;

    int a_row = lane & 15;
    int a_kb  = (lane >> 4) * 16;
    uint32_t a_xor = (uint32_t)(a_row & 7) << 4;
    int b_n  = (lane & 7) + ((lane >> 4) << 3);
    int b_kb = ((lane >> 3) & 1) * 16;
    uint32_t b_xor = (uint32_t)(b_n & 7) << 4;
    uint32_t aOff = (uint32_t)(rbase + a_row) * 128;
    uint32_t bOff0 = (uint32_t)(cbase + b_n) * 128;
    uint32_t bOff1 = bOff0 + 16 * 128;

    for (int chunk = 0; chunk < 4; chunk++) {
        if (chunk < 3) {
            issue_chunk(tb + ((chunk + 1) & 1) * STAGE_BYTES, chunk + 1, ib, jb, tid);
            CPA_WAIT(1);
        } else {
            CPA_WAIT(0);
        }
        __syncthreads();

        uint32_t base = tb + (chunk & 1) * STAGE_BYTES;
        uint32_t tAh = base;
        uint32_t tBh = base + TILE_BYTES, tBl = base + 2 * TILE_BYTES;

#pragma unroll
        for (int ks = 0; ks < 4; ks++) {
            uint32_t kA = ((uint32_t)(ks * 32 + a_kb)) ^ a_xor;
            uint32_t kB = ((uint32_t)(ks * 32 + b_kb)) ^ b_xor;
            uint32_t bh[8], bl[8];
            LDSM4(bh[0], bh[1], bh[2], bh[3], tBh + bOff0 + kB);
            LDSM4(bh[4], bh[5], bh[6], bh[7], tBh + bOff1 + kB);
            LDSM4(bl[0], bl[1], bl[2], bl[3], tBl + bOff0 + kB);
            LDSM4(bl[4], bl[5], bl[6], bl[7], tBl + bOff1 + kB);
#pragma unroll
            for (int mf = 0; mf < 4; mf++) {
                uint32_t ah0, ah1, ah2, ah3;
                LDSM4(ah0, ah1, ah2, ah3, tAh + aOff + mf * 2048 + kA);
                MMA16816(acc[mf][0], ah0, ah1, ah2, ah3, bh[0], bh[1]);
                MMA16816(acc[mf][1], ah0, ah1, ah2, ah3, bh[2], bh[3]);
                MMA16816(acc[mf][2], ah0, ah1, ah2, ah3, bh[4], bh[5]);
                MMA16816(acc[mf][3], ah0, ah1, ah2, ah3, bh[6], bh[7]);
                MMA16816(acc[mf][0], ah0, ah1, ah2, ah3, bl[0], bl[1]);
                MMA16816(acc[mf][1], ah0, ah1, ah2, ah3, bl[2], bl[3]);
                MMA16816(acc[mf][2], ah0, ah1, ah2, ah3, bl[4], bl[5]);
                MMA16816(acc[mf][3], ah0, ah1, ah2, ah3, bl[6], bl[7]);
            }
        }
        __syncthreads();
    }

    int qr = lane >> 2, qc = lane & 3;
    float rmin[8], cmin[8];
#pragma unroll
    for (int i = 0; i < 8; i++) { rmin[i] = BIGF; cmin[i] = BIGF; }

#pragma unroll
    for (int mf = 0; mf < 4; mf++) {
        int la0 = labA[rbase + mf * 16 + qr];
        int la1 = labA[rbase + mf * 16 + qr + 8];
#pragma unroll
        for (int nf = 0; nf < 4; nf++) {
            int c0 = cbase + nf * 8 + qc * 2;
            int lb0 = labB[c0], lb1 = labB[c0 + 1];
            float d0 = fmaxf(1.0f - acc[mf][nf][0], 0.0f);
            float d1 = fmaxf(1.0f - acc[mf][nf][1], 0.0f);
            float d2 = fmaxf(1.0f - acc[mf][nf][2], 0.0f);
            float d3 = fmaxf(1.0f - acc[mf][nf][3], 0.0f);
            float v0 = (la0 != lb0) ? d0 : BIGF;
            float v1 = (la0 != lb1) ? d1 : BIGF;
            float v2 = (la1 != lb0) ? d2 : BIGF;
            float v3 = (la1 != lb1) ? d3 : BIGF;
            rmin[mf * 2 + 0] = fminf(rmin[mf * 2 + 0], fminf(v0, v1));
            rmin[mf * 2 + 1] = fminf(rmin[mf * 2 + 1], fminf(v2, v3));
            cmin[nf * 2 + 0] = fminf(cmin[nf * 2 + 0], fminf(v0, v2));
            cmin[nf * 2 + 1] = fminf(cmin[nf * 2 + 1], fminf(v1, v3));
        }
    }
#pragma unroll
    for (int o = 1; o <= 2; o <<= 1)
#pragma unroll
        for (int i = 0; i < 8; i++)
            rmin[i] = fminf(rmin[i], __shfl_xor_sync(0xFFFFFFFFu, rmin[i], o));
    if (qc == 0) {
#pragma unroll
        for (int mf = 0; mf < 4; mf++) {
            s_rmin[rbase + mf * 16 + qr + 0][wc] = rmin[mf * 2 + 0];
            s_rmin[rbase + mf * 16 + qr + 8][wc] = rmin[mf * 2 + 1];
        }
    }
#pragma unroll
    for (int o = 4; o <= 16; o <<= 1)
#pragma unroll
        for (int i = 0; i < 8; i++)
            cmin[i] = fminf(cmin[i], __shfl_xor_sync(0xFFFFFFFFu, cmin[i], o));
    if (lane < 4) {
#pragma unroll
        for (int nf = 0; nf < 4; nf++) {
            s_cmin[cbase + nf * 8 + lane * 2 + 0][wr] = cmin[nf * 2 + 0];
            s_cmin[cbase + nf * 8 + lane * 2 + 1][wr] = cmin[nf * 2 + 1];
        }
    }
    __syncthreads();
    if (tid < 128) {
        float m = fminf(fminf(s_rmin[tid][0], s_rmin[tid][1]),
                        fminf(s_rmin[tid][2], s_rmin[tid][3]));
        if (m < BIGF) atomicMin(&g_hn_bits[ib + tid], __float_as_uint(m));
        float c = fminf(s_cmin[tid][0], s_cmin[tid][1]);
        if (c < BIGF) atomicMin(&g_hn_bits[jb + tid], __float_as_uint(c));
    }
}

// ---------------- positive-pair losses: single smem copy + cached hn ----------------
__global__ __launch_bounds__(256) void class_loss_k() {
    extern __shared__ float srows[];          // MAXC x 256
    __shared__ float shn[MAXM];
    __shared__ int   smem_idx[MAXM];
    int c = blockIdx.x;
    int m = min(g_cls_cnt[c], MAXM);
    int tid = threadIdx.x;
    int wid = tid >> 5, lane = tid & 31;
    const int* mem = &g_cls_members[c * MAXM];

    for (int r = tid; r < m; r += 256) {
        int row = mem[r];
        smem_idx[r] = row;
        shn[r] = __uint_as_float(g_hn_bits[row]);
    }
    __syncthreads();
    int mc = min(m, MAXC);
    for (int idx = tid; idx < mc * 64; idx += 256)
        ((float4*)srows)[idx] =
            ((const float4*)(g_e + (size_t)smem_idx[idx >> 6] * D_SZ))[idx & 63];
    __syncthreads();

    float lt = 0.0f; int lc = 0;
    int npairs = m * m;
    for (int p = wid; p < npairs; p += 8) {
        int ar = p / m, br = p % m;
        if (ar == br) continue;
        const float4* ea = (ar < MAXC)
            ? (const float4*)(srows + ar * D_SZ) + lane * 2
            : (const float4*)(g_e + (size_t)smem_idx[ar] * D_SZ) + lane * 2;
        const float4* eb = (br < MAXC)
            ? (const float4*)(srows + br * D_SZ) + lane * 2
            : (const float4*)(g_e + (size_t)smem_idx[br] * D_SZ) + lane * 2;
        float4 va0 = ea[0], va1 = ea[1], vb0 = eb[0], vb1 = eb[1];
        float s = va0.x * vb0.x + va0.y * vb0.y + va0.z * vb0.z + va0.w * vb0.w
                + va1.x * vb1.x + va1.y * vb1.y + va1.z * vb1.z + va1.w * vb1.w;
#pragma unroll
        for (int o = 16; o; o >>= 1) s += __shfl_xor_sync(0xFFFFFFFFu, s, o);
        if (lane == 0) {
            float d = fmaxf(1.0f - s, 0.0f);
            float loss = d - shn[ar] + MARGIN;
            if (loss > 0.0f) { lt += loss; lc++; }
        }
    }
    __shared__ float st[8];
    __shared__ int   sc[8];
    if (lane == 0) { st[wid] = lt; sc[wid] = lc; }
    __syncthreads();
    if (tid == 0) {
        float t = 0.0f; int n = 0;
#pragma unroll
        for (int w = 0; w < 8; w++) { t += st[w]; n += sc[w]; }
        if (n > 0) {
            atomicAdd(&g_total, t);
            atomicAdd(&g_count, n);
        }
    }
}

__global__ void finalize_k(float* out) {
    if (threadIdx.x == 0)
        out[0] = (g_count > 0) ? (g_total / (float)g_count) : 0.0f;
}

// ---------------- launch ----------------
extern "C" void kernel_launch(void* const* d_in, const int* in_sizes, int n_in,
                              void* d_out, int out_size) {
    const float* emb = (const float*)d_in[0];
    const int* labels = (const int*)d_in[1];
    float* out = (float*)d_out;
    (void)in_sizes; (void)n_in; (void)out_size;

    static int attr_set = 0;
    if (!attr_set) {
        cudaFuncSetAttribute(min_gemm_hmma,
                             cudaFuncAttributeMaxDynamicSharedMemorySize, SMEM_DYN);
        cudaFuncSetAttribute(class_loss_k,
                             cudaFuncAttributeMaxDynamicSharedMemorySize, CLS_SMEM);
        attr_set = 1;
    }

    pre_k<<<33, 256>>>(labels);
    normalize_k<<<B_SZ / 8, 256>>>(emb, labels);
    min_gemm_hmma<<<TM * (TM + 1) / 2, 256, SMEM_DYN>>>(labels);
    class_loss_k<<<NCLS, 256, CLS_SMEM>>>();
    finalize_k<<<1, 32>>>(out);
}

// round 7
// speedup vs baseline: 1.0933x; 1.0933x over previous
#include <cuda_runtime.h>
#include <cuda_fp16.h>
#include <cstdint>

#define B_SZ 8192
#define D_SZ 256
#define NCLS 512
#define TM 64
#define MARGIN 1.0f
#define BIGF 1e9f
#define PAIR_CAP (2 * 1024 * 1024)

#define TILE_BYTES 16384                   // 128 rows * 128B
#define STAGE_BYTES (3 * TILE_BYTES)       // Ah, Bh, Bl
#define SMEM_DYN (2 * STAGE_BYTES + 1024)  // 97.25 KB -> 2 CTAs/SM

// ---------------- device scratch ----------------
__device__ __half       g_hi[B_SZ * D_SZ];
__device__ __half       g_lo[B_SZ * D_SZ];
__device__ unsigned int g_hn_bits[B_SZ];
__device__ uint2        g_pairs[PAIR_CAP];   // (anchor, dist bits)
__device__ int          g_np;
__device__ float        g_total;
__device__ int          g_count;
__device__ int          g_lab64;

// ---------------- helpers ----------------
__device__ __forceinline__ uint32_t smem_u32(const void* p) {
    uint32_t a;
    asm("{ .reg .u64 t; cvta.to.shared.u64 t, %1; cvt.u32.u64 %0, t; }" : "=r"(a) : "l"(p));
    return a;
}
__device__ __forceinline__ int get_label(const int* l, int i, int is64) {
    return is64 ? l[2 * i] : l[i];
}
__device__ __forceinline__ void emit_pair(int a, float d) {
    int p = atomicAdd(&g_np, 1);
    if (p < PAIR_CAP) g_pairs[p] = make_uint2((unsigned)a, __float_as_uint(d));
}

#define LDSM4(r0, r1, r2, r3, addr)                                              \
    asm volatile("ldmatrix.sync.aligned.m8n8.x4.shared.b16 {%0,%1,%2,%3}, [%4];" \
                 : "=r"(r0), "=r"(r1), "=r"(r2), "=r"(r3) : "r"(addr))

#define MMA16816(d, a0, a1, a2, a3, b0, b1)                                  \
    asm volatile("mma.sync.aligned.m16n8k16.row.col.f32.f16.f16.f32 "        \
                 "{%0,%1,%2,%3}, {%4,%5,%6,%7}, {%8,%9}, {%0,%1,%2,%3};"     \
                 : "+f"(d[0]), "+f"(d[1]), "+f"(d[2]), "+f"(d[3])            \
                 : "r"(a0), "r"(a1), "r"(a2), "r"(a3), "r"(b0), "r"(b1))

#define CPA16(dst, src)                                                       \
    asm volatile("cp.async.cg.shared.global [%0], [%1], 16;"                  \
                 :: "r"(dst), "l"(src) : "memory")
#define CPA_COMMIT asm volatile("cp.async.commit_group;" ::: "memory")
#define CPA_WAIT(n) asm volatile("cp.async.wait_group %0;" :: "n"(n) : "memory")

// ---------------- pre: detect label dtype + reset state ----------------
__global__ void pre_k(const int* __restrict__ labels) {
    if (blockIdx.x == 0) {
        __shared__ int sh[256];
        int acc = 0;
        for (int i = threadIdx.x; i < B_SZ / 2; i += 256) acc |= labels[2 * i + 1];
        sh[threadIdx.x] = acc;
        __syncthreads();
        for (int o = 128; o; o >>= 1) {
            if (threadIdx.x < o) sh[threadIdx.x] |= sh[threadIdx.x + o];
            __syncthreads();
        }
        if (threadIdx.x == 0) g_lab64 = (sh[0] == 0) ? 1 : 0;
    } else {
        int t = (blockIdx.x - 1) * 256 + threadIdx.x;
        if (t < B_SZ) g_hn_bits[t] = __float_as_uint(BIGF);
        if (t == 0) { g_total = 0.0f; g_count = 0; g_np = 0; }
    }
}

// ---------------- normalize (warp/row) + fp16 hi/lo split ----------------
__global__ __launch_bounds__(256) void normalize_k(const float* __restrict__ x) {
    int wid = threadIdx.x >> 5, lane = threadIdx.x & 31;
    int row = blockIdx.x * 8 + wid;
    size_t base = (size_t)row * D_SZ + lane * 8;
    float4 v0 = *(const float4*)(x + base);
    float4 v1 = *(const float4*)(x + base + 4);
    float e[8] = {v0.x, v0.y, v0.z, v0.w, v1.x, v1.y, v1.z, v1.w};
    float s = 0.0f;
#pragma unroll
    for (int q = 0; q < 8; q++) s += e[q] * e[q];
#pragma unroll
    for (int o = 16; o; o >>= 1) s += __shfl_xor_sync(0xFFFFFFFFu, s, o);
    float inv = 1.0f / fmaxf(sqrtf(s), 1e-12f);

    union { __half h[8]; uint4 u; } hi, lo;
#pragma unroll
    for (int q = 0; q < 8; q++) {
        e[q] *= inv;
        __half h = __float2half_rn(e[q]);
        hi.h[q] = h;
        lo.h[q] = __float2half_rn(e[q] - __half2float(h));
    }
    *(uint4*)(g_hi + base) = hi.u;
    *(uint4*)(g_lo + base) = lo.u;
}

// ---------------- HMMA GEMM + masked min + positive-pair emission ----------------
__device__ __forceinline__ void issue_chunk(uint32_t sbase, int chunk, int ib, int jb,
                                            int tid) {
#pragma unroll
    for (int r = 0; r < 4; r++) {
        int idx = tid + 256 * r;
        int row = idx >> 3, seg = idx & 7;
        size_t gofs = (size_t)row * 512 + (size_t)chunk * 128 + (size_t)seg * 16;
        uint32_t off = (uint32_t)(row * 128 + ((seg * 16) ^ ((row & 7) << 4)));
        CPA16(sbase + 0 * TILE_BYTES + off, (const char*)g_hi + (size_t)ib * 512 + gofs);
        CPA16(sbase + 1 * TILE_BYTES + off, (const char*)g_hi + (size_t)jb * 512 + gofs);
        CPA16(sbase + 2 * TILE_BYTES + off, (const char*)g_lo + (size_t)jb * 512 + gofs);
    }
    CPA_COMMIT;
}

__global__ __launch_bounds__(256, 2) void min_gemm_hmma(const int* __restrict__ labels) {
    extern __shared__ char dyn[];
    __shared__ int   labA[128], labB[128];
    __shared__ float s_rmin[128][4];
    __shared__ float s_cmin[128][2];

    int bid = blockIdx.x;
    int bi = 0;
    while (((bi + 1) * (2 * TM - bi)) / 2 <= bid) bi++;
    int bj = bi + (bid - (bi * (2 * TM - bi + 1)) / 2);
    int ib = bi * 128, jb = bj * 128;
    bool offdiag = (bi != bj);

    int tid = threadIdx.x;
    int lane = tid & 31, wid = tid >> 5;
    int wr = wid >> 2, wc = wid & 3;
    int rbase = wr * 64, cbase = wc * 32;
    int is64 = g_lab64;

    uint32_t dbase = smem_u32(dyn);
    uint32_t tb = (dbase + 1023u) & ~1023u;

    if (tid < 128) labA[tid] = get_label(labels, ib + tid, is64);
    else           labB[tid - 128] = get_label(labels, jb + (tid - 128), is64);

    issue_chunk(tb, 0, ib, jb, tid);

    float acc[4][4][4];
#pragma unroll
    for (int mf = 0; mf < 4; mf++)
#pragma unroll
        for (int nf = 0; nf < 4; nf++)
#pragma unroll
            for (int r = 0; r < 4; r++) acc[mf][nf][r] = 0.0f;

    int a_row = lane & 15;
    int a_kb  = (lane >> 4) * 16;
    uint32_t a_xor = (uint32_t)(a_row & 7) << 4;
    int b_n  = (lane & 7) + ((lane >> 4) << 3);
    int b_kb = ((lane >> 3) & 1) * 16;
    uint32_t b_xor = (uint32_t)(b_n & 7) << 4;
    uint32_t aOff = (uint32_t)(rbase + a_row) * 128;
    uint32_t bOff0 = (uint32_t)(cbase + b_n) * 128;
    uint32_t bOff1 = bOff0 + 16 * 128;

    for (int chunk = 0; chunk < 4; chunk++) {
        if (chunk < 3) {
            issue_chunk(tb + ((chunk + 1) & 1) * STAGE_BYTES, chunk + 1, ib, jb, tid);
            CPA_WAIT(1);
        } else {
            CPA_WAIT(0);
        }
        __syncthreads();

        uint32_t base = tb + (chunk & 1) * STAGE_BYTES;
        uint32_t tAh = base;
        uint32_t tBh = base + TILE_BYTES, tBl = base + 2 * TILE_BYTES;

#pragma unroll
        for (int ks = 0; ks < 4; ks++) {
            uint32_t kA = ((uint32_t)(ks * 32 + a_kb)) ^ a_xor;
            uint32_t kB = ((uint32_t)(ks * 32 + b_kb)) ^ b_xor;
            uint32_t bh[8], bl[8];
            LDSM4(bh[0], bh[1], bh[2], bh[3], tBh + bOff0 + kB);
            LDSM4(bh[4], bh[5], bh[6], bh[7], tBh + bOff1 + kB);
            LDSM4(bl[0], bl[1], bl[2], bl[3], tBl + bOff0 + kB);
            LDSM4(bl[4], bl[5], bl[6], bl[7], tBl + bOff1 + kB);
#pragma unroll
            for (int mf = 0; mf < 4; mf++) {
                uint32_t ah0, ah1, ah2, ah3;
                LDSM4(ah0, ah1, ah2, ah3, tAh + aOff + mf * 2048 + kA);
                MMA16816(acc[mf][0], ah0, ah1, ah2, ah3, bh[0], bh[1]);
                MMA16816(acc[mf][1], ah0, ah1, ah2, ah3, bh[2], bh[3]);
                MMA16816(acc[mf][2], ah0, ah1, ah2, ah3, bh[4], bh[5]);
                MMA16816(acc[mf][3], ah0, ah1, ah2, ah3, bh[6], bh[7]);
                MMA16816(acc[mf][0], ah0, ah1, ah2, ah3, bl[0], bl[1]);
                MMA16816(acc[mf][1], ah0, ah1, ah2, ah3, bl[2], bl[3]);
                MMA16816(acc[mf][2], ah0, ah1, ah2, ah3, bl[4], bl[5]);
                MMA16816(acc[mf][3], ah0, ah1, ah2, ah3, bl[6], bl[7]);
            }
        }
        __syncthreads();
    }

    // ---------------- epilogue: mask + min + positive emission ----------------
    int qr = lane >> 2, qc = lane & 3;
    float rmin[8], cmin[8];
#pragma unroll
    for (int i = 0; i < 8; i++) { rmin[i] = BIGF; cmin[i] = BIGF; }

#pragma unroll
    for (int mf = 0; mf < 4; mf++) {
        int r0 = rbase + mf * 16 + qr, r1 = r0 + 8;
        int la0 = labA[r0], la1 = labA[r1];
#pragma unroll
        for (int nf = 0; nf < 4; nf++) {
            int c0 = cbase + nf * 8 + qc * 2, c1 = c0 + 1;
            int lb0 = labB[c0], lb1 = labB[c1];
            float d0 = fmaxf(1.0f - acc[mf][nf][0], 0.0f);
            float d1 = fmaxf(1.0f - acc[mf][nf][1], 0.0f);
            float d2 = fmaxf(1.0f - acc[mf][nf][2], 0.0f);
            float d3 = fmaxf(1.0f - acc[mf][nf][3], 0.0f);
            // positive-pair emission (rare)
            if (la0 == lb0 && (ib + r0) != (jb + c0)) {
                emit_pair(ib + r0, d0);
                if (offdiag) emit_pair(jb + c0, d0);
            }
            if (la0 == lb1 && (ib + r0) != (jb + c1)) {
                emit_pair(ib + r0, d1);
                if (offdiag) emit_pair(jb + c1, d1);
            }
            if (la1 == lb0 && (ib + r1) != (jb + c0)) {
                emit_pair(ib + r1, d2);
                if (offdiag) emit_pair(jb + c0, d2);
            }
            if (la1 == lb1 && (ib + r1) != (jb + c1)) {
                emit_pair(ib + r1, d3);
                if (offdiag) emit_pair(jb + c1, d3);
            }
            // hardest-negative mins
            float v0 = (la0 != lb0) ? d0 : BIGF;
            float v1 = (la0 != lb1) ? d1 : BIGF;
            float v2 = (la1 != lb0) ? d2 : BIGF;
            float v3 = (la1 != lb1) ? d3 : BIGF;
            rmin[mf * 2 + 0] = fminf(rmin[mf * 2 + 0], fminf(v0, v1));
            rmin[mf * 2 + 1] = fminf(rmin[mf * 2 + 1], fminf(v2, v3));
            cmin[nf * 2 + 0] = fminf(cmin[nf * 2 + 0], fminf(v0, v2));
            cmin[nf * 2 + 1] = fminf(cmin[nf * 2 + 1], fminf(v1, v3));
        }
    }
#pragma unroll
    for (int o = 1; o <= 2; o <<= 1)
#pragma unroll
        for (int i = 0; i < 8; i++)
            rmin[i] = fminf(rmin[i], __shfl_xor_sync(0xFFFFFFFFu, rmin[i], o));
    if (qc == 0) {
#pragma unroll
        for (int mf = 0; mf < 4; mf++) {
            s_rmin[rbase + mf * 16 + qr + 0][wc] = rmin[mf * 2 + 0];
            s_rmin[rbase + mf * 16 + qr + 8][wc] = rmin[mf * 2 + 1];
        }
    }
#pragma unroll
    for (int o = 4; o <= 16; o <<= 1)
#pragma unroll
        for (int i = 0; i < 8; i++)
            cmin[i] = fminf(cmin[i], __shfl_xor_sync(0xFFFFFFFFu, cmin[i], o));
    if (lane < 4) {
#pragma unroll
        for (int nf = 0; nf < 4; nf++) {
            s_cmin[cbase + nf * 8 + lane * 2 + 0][wr] = cmin[nf * 2 + 0];
            s_cmin[cbase + nf * 8 + lane * 2 + 1][wr] = cmin[nf * 2 + 1];
        }
    }
    __syncthreads();
    if (tid < 128) {
        float m = fminf(fminf(s_rmin[tid][0], s_rmin[tid][1]),
                        fminf(s_rmin[tid][2], s_rmin[tid][3]));
        if (m < BIGF) atomicMin(&g_hn_bits[ib + tid], __float_as_uint(m));
        float c = fminf(s_cmin[tid][0], s_cmin[tid][1]);
        if (c < BIGF) atomicMin(&g_hn_bits[jb + tid], __float_as_uint(c));
    }
}

// ---------------- pair losses from emitted list ----------------
__global__ __launch_bounds__(256) void pair_loss_k() {
    int n = min(g_np, PAIR_CAP);
    float lt = 0.0f; int lc = 0;
    for (int i = blockIdx.x * 256 + threadIdx.x; i < n; i += gridDim.x * 256) {
        uint2 e = g_pairs[i];
        float d = __uint_as_float(e.y);
        float hn = __uint_as_float(g_hn_bits[e.x]);
        float loss = d - hn + MARGIN;
        if (loss > 0.0f) { lt += loss; lc++; }
    }
    // warp + block reduce
#pragma unroll
    for (int o = 16; o; o >>= 1) {
        lt += __shfl_xor_sync(0xFFFFFFFFu, lt, o);
        lc += __shfl_xor_sync(0xFFFFFFFFu, lc, o);
    }
    __shared__ float st[8];
    __shared__ int   sc[8];
    int wid = threadIdx.x >> 5, lane = threadIdx.x & 31;
    if (lane == 0) { st[wid] = lt; sc[wid] = lc; }
    __syncthreads();
    if (threadIdx.x == 0) {
        float t = 0.0f; int c = 0;
#pragma unroll
        for (int w = 0; w < 8; w++) { t += st[w]; c += sc[w]; }
        if (c > 0) { atomicAdd(&g_total, t); atomicAdd(&g_count, c); }
    }
}

__global__ void finalize_k(float* out) {
    if (threadIdx.x == 0)
        out[0] = (g_count > 0) ? (g_total / (float)g_count) : 0.0f;
}

// ---------------- launch ----------------
extern "C" void kernel_launch(void* const* d_in, const int* in_sizes, int n_in,
                              void* d_out, int out_size) {
    const float* emb = (const float*)d_in[0];
    const int* labels = (const int*)d_in[1];
    float* out = (float*)d_out;
    (void)in_sizes; (void)n_in; (void)out_size;

    static int attr_set = 0;
    if (!attr_set) {
        cudaFuncSetAttribute(min_gemm_hmma,
                             cudaFuncAttributeMaxDynamicSharedMemorySize, SMEM_DYN);
        attr_set = 1;
    }

    pre_k<<<34, 256>>>(labels);
    normalize_k<<<B_SZ / 8, 256>>>(emb);
    min_gemm_hmma<<<TM * (TM + 1) / 2, 256, SMEM_DYN>>>(labels);
    pair_loss_k<<<296, 256>>>();
    finalize_k<<<1, 32>>>(out);
}

// round 9
// speedup vs baseline: 1.2640x; 1.1560x over previous
#include <cuda_runtime.h>
#include <cuda_fp16.h>
#include <cstdint>

#define B_SZ 8192
#define D_SZ 256
#define TM 64
#define MARGIN 1.0f
#define BIGF 1e9f
#define PAIR_CAP (2 * 1024 * 1024)

#define TILE_BYTES 16384                   // 128 rows * 128B
#define STAGE_BYTES (2 * TILE_BYTES)       // Ah, Bh
#define SMEM_DYN (2 * STAGE_BYTES + 1024)  // 65 KB -> 2 CTAs/SM

// ---------------- device scratch ----------------
__device__ __half       g_hi[B_SZ * D_SZ];
__device__ unsigned int g_hn_bits[B_SZ];
__device__ uint2        g_pairs[PAIR_CAP];   // (anchor, dist bits)
__device__ int          g_np;
__device__ float        g_total;
__device__ int          g_count;
__device__ int          g_lab64;

// ---------------- helpers ----------------
__device__ __forceinline__ uint32_t smem_u32(const void* p) {
    uint32_t a;
    asm("{ .reg .u64 t; cvta.to.shared.u64 t, %1; cvt.u32.u64 %0, t; }" : "=r"(a) : "l"(p));
    return a;
}
__device__ __forceinline__ int get_label(const int* l, int i, int is64) {
    return is64 ? l[2 * i] : l[i];
}
__device__ __forceinline__ void emit_pair(int a, float d) {
    int p = atomicAdd(&g_np, 1);
    if (p < PAIR_CAP) g_pairs[p] = make_uint2((unsigned)a, __float_as_uint(d));
}

#define LDSM4(r0, r1, r2, r3, addr)                                              \
    asm volatile("ldmatrix.sync.aligned.m8n8.x4.shared.b16 {%0,%1,%2,%3}, [%4];" \
                 : "=r"(r0), "=r"(r1), "=r"(r2), "=r"(r3) : "r"(addr))

#define MMA16816(d, a0, a1, a2, a3, b0, b1)                                  \
    asm volatile("mma.sync.aligned.m16n8k16.row.col.f32.f16.f16.f32 "        \
                 "{%0,%1,%2,%3}, {%4,%5,%6,%7}, {%8,%9}, {%0,%1,%2,%3};"     \
                 : "+f"(d[0]), "+f"(d[1]), "+f"(d[2]), "+f"(d[3])            \
                 : "r"(a0), "r"(a1), "r"(a2), "r"(a3), "r"(b0), "r"(b1))

#define CPA16(dst, src)                                                       \
    asm volatile("cp.async.cg.shared.global [%0], [%1], 16;"                  \
                 :: "r"(dst), "l"(src) : "memory")
#define CPA_COMMIT asm volatile("cp.async.commit_group;" ::: "memory")
#define CPA_WAIT(n) asm volatile("cp.async.wait_group %0;" :: "n"(n) : "memory")

// ---------------- pre: detect label dtype + reset state ----------------
__global__ void pre_k(const int* __restrict__ labels) {
    if (blockIdx.x == 0) {
        __shared__ int sh[256];
        int acc = 0;
        for (int i = threadIdx.x; i < B_SZ / 2; i += 256) acc |= labels[2 * i + 1];
        sh[threadIdx.x] = acc;
        __syncthreads();
        for (int o = 128; o; o >>= 1) {
            if (threadIdx.x < o) sh[threadIdx.x] |= sh[threadIdx.x + o];
            __syncthreads();
        }
        if (threadIdx.x == 0) g_lab64 = (sh[0] == 0) ? 1 : 0;
    } else {
        int t = (blockIdx.x - 1) * 256 + threadIdx.x;
        if (t < B_SZ) g_hn_bits[t] = __float_as_uint(BIGF);
        if (t == 0) { g_total = 0.0f; g_count = 0; g_np = 0; }
    }
}

// ---------------- normalize (warp/row) -> fp16 ----------------
__global__ __launch_bounds__(256) void normalize_k(const float* __restrict__ x) {
    int wid = threadIdx.x >> 5, lane = threadIdx.x & 31;
    int row = blockIdx.x * 8 + wid;
    size_t base = (size_t)row * D_SZ + lane * 8;
    float4 v0 = *(const float4*)(x + base);
    float4 v1 = *(const float4*)(x + base + 4);
    float e[8] = {v0.x, v0.y, v0.z, v0.w, v1.x, v1.y, v1.z, v1.w};
    float s = 0.0f;
#pragma unroll
    for (int q = 0; q < 8; q++) s += e[q] * e[q];
#pragma unroll
    for (int o = 16; o; o >>= 1) s += __shfl_xor_sync(0xFFFFFFFFu, s, o);
    float inv = 1.0f / fmaxf(sqrtf(s), 1e-12f);

    union { __half h[8]; uint4 u; } hi;
#pragma unroll
    for (int q = 0; q < 8; q++) hi.h[q] = __float2half_rn(e[q] * inv);
    *(uint4*)(g_hi + base) = hi.u;
}

// ---------------- HMMA GEMM + masked min + positive-pair emission ----------------
__device__ __forceinline__ void issue_chunk(uint32_t sbase, int chunk, int ib, int jb,
                                            int tid) {
#pragma unroll
    for (int r = 0; r < 4; r++) {
        int idx = tid + 256 * r;
        int row = idx >> 3, seg = idx & 7;
        size_t gofs = (size_t)row * 512 + (size_t)chunk * 128 + (size_t)seg * 16;
        uint32_t off = (uint32_t)(row * 128 + ((seg * 16) ^ ((row & 7) << 4)));
        CPA16(sbase + 0 * TILE_BYTES + off, (const char*)g_hi + (size_t)ib * 512 + gofs);
        CPA16(sbase + 1 * TILE_BYTES + off, (const char*)g_hi + (size_t)jb * 512 + gofs);
    }
    CPA_COMMIT;
}

__global__ __launch_bounds__(256, 2) void min_gemm_hmma(const int* __restrict__ labels) {
    extern __shared__ char dyn[];
    __shared__ int   labA[128], labB[128];
    __shared__ float s_rmin[128][4];
    __shared__ float s_cmin[128][2];

    int bid = blockIdx.x;
    int bi = 0;
    while (((bi + 1) * (2 * TM - bi)) / 2 <= bid) bi++;
    int bj = bi + (bid - (bi * (2 * TM - bi + 1)) / 2);
    int ib = bi * 128, jb = bj * 128;
    bool offdiag = (bi != bj);

    int tid = threadIdx.x;
    int lane = tid & 31, wid = tid >> 5;
    int wr = wid >> 2, wc = wid & 3;
    int rbase = wr * 64, cbase = wc * 32;
    int is64 = g_lab64;

    uint32_t dbase = smem_u32(dyn);
    uint32_t tb = (dbase + 1023u) & ~1023u;

    if (tid < 128) labA[tid] = get_label(labels, ib + tid, is64);
    else           labB[tid - 128] = get_label(labels, jb + (tid - 128), is64);

    issue_chunk(tb, 0, ib, jb, tid);

    float acc[4][4][4];
#pragma unroll
    for (int mf = 0; mf < 4; mf++)
#pragma unroll
        for (int nf = 0; nf < 4; nf++)
#pragma unroll
            for (int r = 0; r < 4; r++) acc[mf][nf][r] = 0.0f;

    int a_row = lane & 15;
    int a_kb  = (lane >> 4) * 16;
    uint32_t a_xor = (uint32_t)(a_row & 7) << 4;
    int b_n  = (lane & 7) + ((lane >> 4) << 3);
    int b_kb = ((lane >> 3) & 1) * 16;
    uint32_t b_xor = (uint32_t)(b_n & 7) << 4;
    uint32_t aOff = (uint32_t)(rbase + a_row) * 128;
    uint32_t bOff0 = (uint32_t)(cbase + b_n) * 128;
    uint32_t bOff1 = bOff0 + 16 * 128;

    for (int chunk = 0; chunk < 4; chunk++) {
        if (chunk < 3) {
            issue_chunk(tb + ((chunk + 1) & 1) * STAGE_BYTES, chunk + 1, ib, jb, tid);
            CPA_WAIT(1);
        } else {
            CPA_WAIT(0);
        }
        __syncthreads();

        uint32_t base = tb + (chunk & 1) * STAGE_BYTES;
        uint32_t tAh = base;
        uint32_t tBh = base + TILE_BYTES;

#pragma unroll
        for (int ks = 0; ks < 4; ks++) {
            uint32_t kA = ((uint32_t)(ks * 32 + a_kb)) ^ a_xor;
            uint32_t kB = ((uint32_t)(ks * 32 + b_kb)) ^ b_xor;
            uint32_t bh[8];
            LDSM4(bh[0], bh[1], bh[2], bh[3], tBh + bOff0 + kB);
            LDSM4(bh[4], bh[5], bh[6], bh[7], tBh + bOff1 + kB);
#pragma unroll
            for (int mf = 0; mf < 4; mf++) {
                uint32_t ah0, ah1, ah2, ah3;
                LDSM4(ah0, ah1, ah2, ah3, tAh + aOff + mf * 2048 + kA);
                MMA16816(acc[mf][0], ah0, ah1, ah2, ah3, bh[0], bh[1]);
                MMA16816(acc[mf][1], ah0, ah1, ah2, ah3, bh[2], bh[3]);
                MMA16816(acc[mf][2], ah0, ah1, ah2, ah3, bh[4], bh[5]);
                MMA16816(acc[mf][3], ah0, ah1, ah2, ah3, bh[6], bh[7]);
            }
        }
        __syncthreads();
    }

    // ---------------- epilogue: mask + min + positive emission ----------------
    int qr = lane >> 2, qc = lane & 3;
    float rmin[8], cmin[8];
#pragma unroll
    for (int i = 0; i < 8; i++) { rmin[i] = BIGF; cmin[i] = BIGF; }

#pragma unroll
    for (int mf = 0; mf < 4; mf++) {
        int r0 = rbase + mf * 16 + qr, r1 = r0 + 8;
        int la0 = labA[r0], la1 = labA[r1];
#pragma unroll
        for (int nf = 0; nf < 4; nf++) {
            int c0 = cbase + nf * 8 + qc * 2, c1 = c0 + 1;
            int lb0 = labB[c0], lb1 = labB[c1];
            float d0 = fmaxf(1.0f - acc[mf][nf][0], 0.0f);
            float d1 = fmaxf(1.0f - acc[mf][nf][1], 0.0f);
            float d2 = fmaxf(1.0f - acc[mf][nf][2], 0.0f);
            float d3 = fmaxf(1.0f - acc[mf][nf][3], 0.0f);
            if (la0 == lb0 && (ib + r0) != (jb + c0)) {
                emit_pair(ib + r0, d0);
                if (offdiag) emit_pair(jb + c0, d0);
            }
            if (la0 == lb1 && (ib + r0) != (jb + c1)) {
                emit_pair(ib + r0, d1);
                if (offdiag) emit_pair(jb + c1, d1);
            }
            if (la1 == lb0 && (ib + r1) != (jb + c0)) {
                emit_pair(ib + r1, d2);
                if (offdiag) emit_pair(jb + c0, d2);
            }
            if (la1 == lb1 && (ib + r1) != (jb + c1)) {
                emit_pair(ib + r1, d3);
                if (offdiag) emit_pair(jb + c1, d3);
            }
            float v0 = (la0 != lb0) ? d0 : BIGF;
            float v1 = (la0 != lb1) ? d1 : BIGF;
            float v2 = (la1 != lb0) ? d2 : BIGF;
            float v3 = (la1 != lb1) ? d3 : BIGF;
            rmin[mf * 2 + 0] = fminf(rmin[mf * 2 + 0], fminf(v0, v1));
            rmin[mf * 2 + 1] = fminf(rmin[mf * 2 + 1], fminf(v2, v3));
            cmin[nf * 2 + 0] = fminf(cmin[nf * 2 + 0], fminf(v0, v2));
            cmin[nf * 2 + 1] = fminf(cmin[nf * 2 + 1], fminf(v1, v3));
        }
    }
#pragma unroll
    for (int o = 1; o <= 2; o <<= 1)
#pragma unroll
        for (int i = 0; i < 8; i++)
            rmin[i] = fminf(rmin[i], __shfl_xor_sync(0xFFFFFFFFu, rmin[i], o));
    if (qc == 0) {
#pragma unroll
        for (int mf = 0; mf < 4; mf++) {
            s_rmin[rbase + mf * 16 + qr + 0][wc] = rmin[mf * 2 + 0];
            s_rmin[rbase + mf * 16 + qr + 8][wc] = rmin[mf * 2 + 1];
        }
    }
#pragma unroll
    for (int o = 4; o <= 16; o <<= 1)
#pragma unroll
        for (int i = 0; i < 8; i++)
            cmin[i] = fminf(cmin[i], __shfl_xor_sync(0xFFFFFFFFu, cmin[i], o));
    if (lane < 4) {
#pragma unroll
        for (int nf = 0; nf < 4; nf++) {
            s_cmin[cbase + nf * 8 + lane * 2 + 0][wr] = cmin[nf * 2 + 0];
            s_cmin[cbase + nf * 8 + lane * 2 + 1][wr] = cmin[nf * 2 + 1];
        }
    }
    __syncthreads();
    if (tid < 128) {
        float m = fminf(fminf(s_rmin[tid][0], s_rmin[tid][1]),
                        fminf(s_rmin[tid][2], s_rmin[tid][3]));
        if (m < BIGF) atomicMin(&g_hn_bits[ib + tid], __float_as_uint(m));
        float c = fminf(s_cmin[tid][0], s_cmin[tid][1]);
        if (c < BIGF) atomicMin(&g_hn_bits[jb + tid], __float_as_uint(c));
    }
}

// ---------------- pair losses from emitted list ----------------
__global__ __launch_bounds__(256) void pair_loss_k() {
    int n = min(g_np, PAIR_CAP);
    float lt = 0.0f; int lc = 0;
    for (int i = blockIdx.x * 256 + threadIdx.x; i < n; i += gridDim.x * 256) {
        uint2 e = g_pairs[i];
        float d = __uint_as_float(e.y);
        float hn = __uint_as_float(g_hn_bits[e.x]);
        float loss = d - hn + MARGIN;
        if (loss > 0.0f) { lt += loss; lc++; }
    }
#pragma unroll
    for (int o = 16; o; o >>= 1) {
        lt += __shfl_xor_sync(0xFFFFFFFFu, lt, o);
        lc += __shfl_xor_sync(0xFFFFFFFFu, lc, o);
    }
    __shared__ float st[8];
    __shared__ int   sc[8];
    int wid = threadIdx.x >> 5, lane = threadIdx.x & 31;
    if (lane == 0) { st[wid] = lt; sc[wid] = lc; }
    __syncthreads();
    if (threadIdx.x == 0) {
        float t = 0.0f; int c = 0;
#pragma unroll
        for (int w = 0; w < 8; w++) { t += st[w]; c += sc[w]; }
        if (c > 0) { atomicAdd(&g_total, t); atomicAdd(&g_count, c); }
    }
}

__global__ void finalize_k(float* out) {
    if (threadIdx.x == 0)
        out[0] = (g_count > 0) ? (g_total / (float)g_count) : 0.0f;
}

// ---------------- launch ----------------
extern "C" void kernel_launch(void* const* d_in, const int* in_sizes, int n_in,
                              void* d_out, int out_size) {
    const float* emb = (const float*)d_in[0];
    const int* labels = (const int*)d_in[1];
    float* out = (float*)d_out;
    (void)in_sizes; (void)n_in; (void)out_size;

    static int attr_set = 0;
    if (!attr_set) {
        cudaFuncSetAttribute(min_gemm_hmma,
                             cudaFuncAttributeMaxDynamicSharedMemorySize, SMEM_DYN);
        attr_set = 1;
    }

    pre_k<<<34, 256>>>(labels);
    normalize_k<<<B_SZ / 8, 256>>>(emb);
    min_gemm_hmma<<<TM * (TM + 1) / 2, 256, SMEM_DYN>>>(labels);
    pair_loss_k<<<296, 256>>>();
    finalize_k<<<1, 32>>>(out);
}